// round 6
// baseline (speedup 1.0000x reference)
#include <cuda_runtime.h>
#include <cuda_bf16.h>
#include <stdint.h>

#define B_ 8
#define T_ 2048
#define D_ 1024
#define SCALE_ 0.03125f   // 1/sqrt(1024)

// k_qk config (unchanged from R5)
#define NSTAGE 3
#define A_BYTES 8192        // 64 rows x 128B
#define B_BYTES 16384       // 128 rows x 128B
#define STAGE_BYTES (A_BYTES + B_BYTES)   // 24576

// k_av big-tile config
#define AV_NSTAGE 4
#define AV_A_BYTES 16384    // 128 rows x 128B
#define AV_B_BYTES 32768    // 256 rows x 128B
#define AV_STAGE (AV_A_BYTES + AV_B_BYTES)   // 49152

// ---------------------------------------------------------------------------
// Scratch
// ---------------------------------------------------------------------------
__device__ __nv_bfloat16 g_Xh [(size_t)B_ * T_ * D_];
__device__ __nv_bfloat16 g_XhT[(size_t)B_ * D_ * T_];
__device__ __nv_bfloat16 g_Sh [(size_t)B_ * T_ * T_];
__device__ float         g_C  [(size_t)B_ * T_ * D_];
__device__ float         g_den[B_ * T_];

// ---------------------------------------------------------------------------
// Helpers
// ---------------------------------------------------------------------------
__device__ __forceinline__ uint32_t smem_u32(const void* p) {
    uint32_t a;
    asm("{ .reg .u64 t; cvta.to.shared.u64 t, %1; cvt.u32.u64 %0, t; }"
        : "=r"(a) : "l"(p));
    return a;
}

__device__ __forceinline__ void cp16(uint32_t dst, const void* src) {
    asm volatile("cp.async.cg.shared.global [%0], [%1], 16;"
                 :: "r"(dst), "l"(src) : "memory");
}
#define CP_COMMIT() asm volatile("cp.async.commit_group;" ::: "memory")
#define CP_WAIT(N)  asm volatile("cp.async.wait_group %0;" :: "n"(N) : "memory")

__device__ __forceinline__ void ldmx4(uint32_t& r0, uint32_t& r1,
                                      uint32_t& r2, uint32_t& r3, uint32_t addr) {
    asm volatile("ldmatrix.sync.aligned.m8n8.x4.shared.b16 {%0,%1,%2,%3}, [%4];"
                 : "=r"(r0), "=r"(r1), "=r"(r2), "=r"(r3) : "r"(addr));
}

__device__ __forceinline__ void mma16816(float* c, const uint32_t* a,
                                         uint32_t b0, uint32_t b1) {
    asm volatile(
        "mma.sync.aligned.m16n8k16.row.col.f32.bf16.bf16.f32 "
        "{%0,%1,%2,%3}, {%4,%5,%6,%7}, {%8,%9}, {%0,%1,%2,%3};"
        : "+f"(c[0]), "+f"(c[1]), "+f"(c[2]), "+f"(c[3])
        : "r"(a[0]), "r"(a[1]), "r"(a[2]), "r"(a[3]), "r"(b0), "r"(b1));
}

__device__ __forceinline__ uint32_t sw128(uint32_t off) {
    return off ^ ((off >> 3) & 0x70);
}

__device__ __forceinline__ float softplusf_(float v) {
    return v > 20.f ? v : log1pf(__expf(v));
}
__device__ __forceinline__ float gelu_tanh_(float v) {
    float u = 0.7978845608028654f * (v + 0.044715f * v * v * v);
    return 0.5f * v * (1.f + tanhf(u));
}

// FFMA-pipe 2^z: magic-number round + deg-4 poly + exponent bit add.
// |rel err| < ~7e-4 for z in [-30, 30] — well under bf16 storage quantization.
__device__ __forceinline__ float fexp2p(float z) {
    float m = z + 12582912.f;         // 2^23 * 1.5 magic: RN to int in mantissa
    float n = m - 12582912.f;         // n = rint(z)
    float f = z - n;                  // f in [-0.5, 0.5]
    float p = 0.0096180f;             // ln2^4/24
    p = fmaf(p, f, 0.0555041f);       // ln2^3/6
    p = fmaf(p, f, 0.2402265f);       // ln2^2/2
    p = fmaf(p, f, 0.6931472f);       // ln2
    p = fmaf(p, f, 1.0f);
    int bits = __float_as_int(p) + (__float_as_int(m) << 23);
    return __int_as_float(bits);
}

// ---------------------------------------------------------------------------
// Kernel 0: convert x -> bf16 (row-major and transposed)
// ---------------------------------------------------------------------------
__global__ __launch_bounds__(256) void k_cvt(const float* __restrict__ x) {
    __shared__ __nv_bfloat16 tile[32][34];
    const int b  = blockIdx.z;
    const int t0 = blockIdx.x * 32;
    const int d0 = blockIdx.y * 32;
    const int lx = threadIdx.x;
    const int ly = threadIdx.y;
    const float* X = x + (size_t)b * T_ * D_;

#pragma unroll
    for (int r = 0; r < 2; r++) {
        const int t = t0 + ly + r * 16;
        const int d = d0 + lx * 2;
        float2 v = *(const float2*)(X + (size_t)t * D_ + d);
        __nv_bfloat162 h = __floats2bfloat162_rn(v.x, v.y);
        *(uint32_t*)(g_Xh + (size_t)(b * T_ + t) * D_ + d) = *(uint32_t*)&h;
        tile[ly + r * 16][lx * 2 + 0] = h.x;
        tile[ly + r * 16][lx * 2 + 1] = h.y;
    }
    __syncthreads();
#pragma unroll
    for (int r = 0; r < 2; r++) {
        const int d  = d0 + ly + r * 16;
        const int tp = lx * 2;
        __nv_bfloat162 h;
        h.x = tile[tp + 0][ly + r * 16];
        h.y = tile[tp + 1][ly + r * 16];
        *(uint32_t*)(g_XhT + ((size_t)b * D_ + d) * T_ + t0 + tp) = *(uint32_t*)&h;
    }
}

// ---------------------------------------------------------------------------
// k_qk MMA core (R5: CTA 64x128, 8 warps 2m x 4n of 32x32)
// ---------------------------------------------------------------------------
__device__ __forceinline__ void mma_chunk(uint32_t sA, uint32_t sB,
                                          int warp_m, int warp_n, int lane,
                                          float c[2][4][4]) {
    const int rowsel = lane & 15;
    const int khalf  = (lane >> 4) * 16;
    const uint32_t a0 = sA + (warp_m * 32 + 0  + rowsel) * 128;
    const uint32_t a1 = sA + (warp_m * 32 + 16 + rowsel) * 128;
    const uint32_t b0a = sB + (warp_n * 32 + 0  + rowsel) * 128;
    const uint32_t b1a = sB + (warp_n * 32 + 16 + rowsel) * 128;
    const uint32_t xa0 = ((warp_m * 32 + 0  + rowsel) & 7) << 4;
    const uint32_t xa1 = ((warp_m * 32 + 16 + rowsel) & 7) << 4;
    const uint32_t xb0 = ((warp_n * 32 + 0  + rowsel) & 7) << 4;
    const uint32_t xb1 = ((warp_n * 32 + 16 + rowsel) & 7) << 4;
#pragma unroll
    for (int ks = 0; ks < 4; ks++) {
        const uint32_t kb = ks * 32 + khalf;
        uint32_t a[2][4];
        ldmx4(a[0][0], a[0][1], a[0][2], a[0][3], a0 + (kb ^ xa0));
        ldmx4(a[1][0], a[1][1], a[1][2], a[1][3], a1 + (kb ^ xa1));
        uint32_t b[4][2];
        {
            uint32_t r0, r1, r2, r3;
            ldmx4(r0, r1, r2, r3, b0a + (kb ^ xb0));
            b[0][0] = r0; b[1][0] = r1; b[0][1] = r2; b[1][1] = r3;
            ldmx4(r0, r1, r2, r3, b1a + (kb ^ xb1));
            b[2][0] = r0; b[3][0] = r1; b[2][1] = r2; b[3][1] = r3;
        }
#pragma unroll
        for (int mi = 0; mi < 2; mi++)
#pragma unroll
            for (int ni = 0; ni < 4; ni++)
                mma16816(c[mi][ni], a[mi], b[ni][0], b[ni][1]);
    }
}

__device__ __forceinline__ void load_tileA64(uint32_t sdst,
                                             const __nv_bfloat16* __restrict__ src,
                                             size_t row_stride, int tid) {
    const int row = tid >> 2;
    const int cb  = (tid & 3) * 2;
    const __nv_bfloat16* g = src + (size_t)row * row_stride + cb * 8;
#pragma unroll
    for (int c = 0; c < 2; c++)
        cp16(sdst + sw128(row * 128 + (cb + c) * 16), g + c * 8);
}
__device__ __forceinline__ void load_tileB128(uint32_t sdst,
                                              const __nv_bfloat16* __restrict__ src,
                                              size_t row_stride, int tid) {
    const int row = tid >> 1;
    const int cb  = (tid & 1) * 4;
    const __nv_bfloat16* g = src + (size_t)row * row_stride + cb * 8;
#pragma unroll
    for (int c = 0; c < 4; c++)
        cp16(sdst + sw128(row * 128 + (cb + c) * 16), g + c * 8);
}

// ---------------------------------------------------------------------------
// Kernel 1: S = exp(SCALE * X X^T) bf16, strict causal. Hybrid-exp epilogue.
// ---------------------------------------------------------------------------
__global__ __launch_bounds__(256, 3) void k_qk_mma() {
    const int sb  = blockIdx.x;
    const int tb6 = blockIdx.y;
    const int b   = blockIdx.z;
    if (sb > (tb6 >> 1)) return;

    extern __shared__ __align__(1024) char smem[];
    const uint32_t sbase = smem_u32(smem);
    const int tid = threadIdx.x, lane = tid & 31, wid = tid >> 5;
    const int warp_m = wid & 1, warp_n = wid >> 1;

    const __nv_bfloat16* A0 = g_Xh + (size_t)(b * T_ + tb6 * 64)  * D_;
    const __nv_bfloat16* B0 = g_Xh + (size_t)(b * T_ + sb * 128)  * D_;

    float c[2][4][4];
#pragma unroll
    for (int mi = 0; mi < 2; mi++)
#pragma unroll
        for (int ni = 0; ni < 4; ni++)
#pragma unroll
            for (int k = 0; k < 4; k++) c[mi][ni][k] = 0.f;

    const int nIter = D_ / 64;
#pragma unroll
    for (int s = 0; s < NSTAGE - 1; s++) {
        const uint32_t st = sbase + s * STAGE_BYTES;
        load_tileA64(st,           A0 + s * 64, D_, tid);
        load_tileB128(st + A_BYTES, B0 + s * 64, D_, tid);
        CP_COMMIT();
    }

    for (int it = 0; it < nIter; ++it) {
        if (it + NSTAGE - 1 < nIter) CP_WAIT(NSTAGE - 2); else CP_WAIT(0);
        __syncthreads();
        if (it + NSTAGE - 1 < nIter) {
            const int ld = it + NSTAGE - 1;
            const uint32_t stb = sbase + (ld % NSTAGE) * STAGE_BYTES;
            load_tileA64(stb,           A0 + ld * 64, D_, tid);
            load_tileB128(stb + A_BYTES, B0 + ld * 64, D_, tid);
            CP_COMMIT();
        }
        const uint32_t st = sbase + (it % NSTAGE) * STAGE_BYTES;
        mma_chunk(st, st + A_BYTES, warp_m, warp_n, lane, c);
    }

    // epilogue: hybrid exp (37.5% FFMA-poly / 62.5% MUFU) + strict mask
    const int quad = lane >> 2, qid = lane & 3;
    const float C2 = 0.045084219f;   // SCALE * log2(e)
#pragma unroll
    for (int mi = 0; mi < 2; mi++) {
#pragma unroll
        for (int ni = 0; ni < 4; ni++) {
            const int col = warp_n * 32 + ni * 8 + qid * 2;
            const int s0  = sb * 128 + col;
#pragma unroll
            for (int h = 0; h < 2; h++) {
                const int row = warp_m * 32 + mi * 16 + quad + h * 8;
                const int t   = tb6 * 64 + row;
                const bool poly = (h == 0) && (ni != 3);   // 6/16 pairs
                float e0, e1;
                if (poly) {
                    e0 = fexp2p(c[mi][ni][2 * h + 0] * C2);
                    e1 = fexp2p(c[mi][ni][2 * h + 1] * C2);
                } else {
                    e0 = __expf(c[mi][ni][2 * h + 0] * SCALE_);
                    e1 = __expf(c[mi][ni][2 * h + 1] * SCALE_);
                }
                float v0 = (s0 + 0 < t) ? e0 : 0.f;
                float v1 = (s0 + 1 < t) ? e1 : 0.f;
                __nv_bfloat162 hv = __floats2bfloat162_rn(v0, v1);
                *(uint32_t*)(g_Sh + ((size_t)(b * T_ + t)) * T_ + s0) = *(uint32_t*)&hv;
            }
        }
    }
}

// ---------------------------------------------------------------------------
// Kernel 2: denominators
// ---------------------------------------------------------------------------
__global__ __launch_bounds__(256) void k_denom() {
    const int warp = (blockIdx.x * 256 + threadIdx.x) >> 5;
    const int lane = threadIdx.x & 31;
    if (warp >= B_ * T_) return;
    const int b = warp / T_, t = warp % T_;
    const int Kmax = ((t >> 7) + 1) << 7;
    const __nv_bfloat162* row2 =
        (const __nv_bfloat162*)(g_Sh + ((size_t)b * T_ + t) * T_);
    float s = 0.f;
    const int np = Kmax >> 1;
    for (int j = lane; j < np; j += 32) {
        float2 f = __bfloat1622float2(row2[j]);
        s += f.x + f.y;
    }
#pragma unroll
    for (int o = 16; o; o >>= 1) s += __shfl_down_sync(0xFFFFFFFFu, s, o);
    if (lane == 0) g_den[warp] = s;
}

// ---------------------------------------------------------------------------
// Kernel 3: context = (S @ X) / den. CTA 128(t) x 256(d), 8 warps of 64x64.
// 4-stage cp.async, 1 CTA/SM, heavy tiles first.
// ---------------------------------------------------------------------------
__global__ __launch_bounds__(256, 1) void k_av_mma() {
    const int nb  = blockIdx.x;                      // d block (256 wide)
    const int tbB = 15 - (int)blockIdx.y;            // t block (128), heavy-first
    const int b   = blockIdx.z;

    extern __shared__ __align__(1024) char smem[];
    const uint32_t sbase = smem_u32(smem);
    const int tid = threadIdx.x, lane = tid & 31, wid = tid >> 5;
    const int warp_m = wid & 1, warp_n = wid >> 1;   // 2m x 4n of 64x64

    const __nv_bfloat16* A0 = g_Sh  + (size_t)(b * T_ + tbB * 128) * T_;
    const __nv_bfloat16* B0 = g_XhT + ((size_t)b * D_ + nb * 256) * T_;

    float c[4][8][4];
#pragma unroll
    for (int mi = 0; mi < 4; mi++)
#pragma unroll
        for (int ni = 0; ni < 8; ni++)
#pragma unroll
            for (int k = 0; k < 4; k++) c[mi][ni][k] = 0.f;

    const int nIter = (tbB + 1) * 2;   // K in 64-chunks

    // loads: A 128 rows (tid>>1), B 256 rows (tid owns full row)
#pragma unroll
    for (int s = 0; s < AV_NSTAGE - 1; s++) {
        if (s < nIter) {
            const uint32_t st = sbase + s * AV_STAGE;
            {
                const int row = tid >> 1, cb = (tid & 1) * 4;
                const __nv_bfloat16* g = A0 + (size_t)row * T_ + s * 64 + cb * 8;
#pragma unroll
                for (int cc = 0; cc < 4; cc++)
                    cp16(st + sw128(row * 128 + (cb + cc) * 16), g + cc * 8);
            }
            {
                const __nv_bfloat16* g = B0 + (size_t)tid * T_ + s * 64;
#pragma unroll
                for (int cc = 0; cc < 8; cc++)
                    cp16(st + AV_A_BYTES + sw128(tid * 128 + cc * 16), g + cc * 8);
            }
            CP_COMMIT();
        }
    }

    const int rowsel = lane & 15;
    const int khalf  = (lane >> 4) * 16;

    for (int it = 0; it < nIter; ++it) {
        if (it + AV_NSTAGE - 1 < nIter) CP_WAIT(AV_NSTAGE - 2); else CP_WAIT(0);
        __syncthreads();
        if (it + AV_NSTAGE - 1 < nIter) {
            const int ld = it + AV_NSTAGE - 1;
            const uint32_t stb = sbase + (ld % AV_NSTAGE) * AV_STAGE;
            {
                const int row = tid >> 1, cb = (tid & 1) * 4;
                const __nv_bfloat16* g = A0 + (size_t)row * T_ + ld * 64 + cb * 8;
#pragma unroll
                for (int cc = 0; cc < 4; cc++)
                    cp16(stb + sw128(row * 128 + (cb + cc) * 16), g + cc * 8);
            }
            {
                const __nv_bfloat16* g = B0 + (size_t)tid * T_ + ld * 64;
#pragma unroll
                for (int cc = 0; cc < 8; cc++)
                    cp16(stb + AV_A_BYTES + sw128(tid * 128 + cc * 16), g + cc * 8);
            }
            CP_COMMIT();
        }

        const uint32_t sA = sbase + (it % AV_NSTAGE) * AV_STAGE;
        const uint32_t sB = sA + AV_A_BYTES;
#pragma unroll
        for (int ks = 0; ks < 4; ks++) {
            const uint32_t kb = ks * 32 + khalf;
            uint32_t a[4][4];
#pragma unroll
            for (int mi = 0; mi < 4; mi++) {
                const uint32_t row = warp_m * 64 + mi * 16 + rowsel;
                ldmx4(a[mi][0], a[mi][1], a[mi][2], a[mi][3],
                      sA + row * 128 + (kb ^ ((row & 7) << 4)));
            }
            uint32_t bf[8][2];
#pragma unroll
            for (int nj = 0; nj < 4; nj++) {
                const uint32_t nrow = warp_n * 64 + nj * 16 + rowsel;
                uint32_t r0, r1, r2, r3;
                ldmx4(r0, r1, r2, r3, sB + nrow * 128 + (kb ^ ((nrow & 7) << 4)));
                bf[nj * 2 + 0][0] = r0; bf[nj * 2 + 1][0] = r1;
                bf[nj * 2 + 0][1] = r2; bf[nj * 2 + 1][1] = r3;
            }
#pragma unroll
            for (int mi = 0; mi < 4; mi++)
#pragma unroll
                for (int ni = 0; ni < 8; ni++)
                    mma16816(c[mi][ni], a[mi], bf[ni][0], bf[ni][1]);
        }
    }

    // epilogue: divide by denom, fp32 store
    const int quad = lane >> 2, qid = lane & 3;
#pragma unroll
    for (int mi = 0; mi < 4; mi++) {
#pragma unroll
        for (int h = 0; h < 2; h++) {
            const int row = warp_m * 64 + mi * 16 + quad + h * 8;
            const int t   = tbB * 128 + row;
            const float den = g_den[b * T_ + t];
            const float inv = den > 0.f ? 1.f / den : 0.f;
            float* crow = g_C + ((size_t)(b * T_ + t)) * D_ + nb * 256;
#pragma unroll
            for (int ni = 0; ni < 8; ni++) {
                const int col = warp_n * 64 + ni * 8 + qid * 2;
                float2 v;
                v.x = c[mi][ni][2 * h + 0] * inv;
                v.y = c[mi][ni][2 * h + 1] * inv;
                *(float2*)(crow + col) = v;
            }
        }
    }
}

// ---------------------------------------------------------------------------
// Kernel 4: cosine / novelty / gate / tanh-GELU
// ---------------------------------------------------------------------------
__global__ __launch_bounds__(256) void k_epi(const float* __restrict__ x,
                                             const float* __restrict__ p_la,
                                             const float* __restrict__ p_ls,
                                             float* __restrict__ out) {
    const int row = blockIdx.x;
    const int tid = threadIdx.x;
    const float4 xv = *((const float4*)x   + (size_t)row * 256 + tid);
    const float4 cv = *((const float4*)g_C + (size_t)row * 256 + tid);

    float xx = xv.x * xv.x + xv.y * xv.y + xv.z * xv.z + xv.w * xv.w;
    float cc = cv.x * cv.x + cv.y * cv.y + cv.z * cv.z + cv.w * cv.w;
    float xc = xv.x * cv.x + xv.y * cv.y + xv.z * cv.z + xv.w * cv.w;

#pragma unroll
    for (int o = 16; o; o >>= 1) {
        xx += __shfl_down_sync(0xFFFFFFFFu, xx, o);
        cc += __shfl_down_sync(0xFFFFFFFFu, cc, o);
        xc += __shfl_down_sync(0xFFFFFFFFu, xc, o);
    }

    __shared__ float s_xx[8], s_cc[8], s_xc[8];
    __shared__ float s_gate;
    const int lane = tid & 31, w = tid >> 5;
    if (lane == 0) { s_xx[w] = xx; s_cc[w] = cc; s_xc[w] = xc; }
    __syncthreads();
    if (tid == 0) {
        float fxx = 0.f, fcc = 0.f, fxc = 0.f;
#pragma unroll
        for (int k = 0; k < 8; k++) { fxx += s_xx[k]; fcc += s_cc[k]; fxc += s_xc[k]; }
        const float nx = fmaxf(sqrtf(fxx), 1e-12f);
        const float nc = fmaxf(sqrtf(fcc), 1e-12f);
        const float cosv = fxc / (nx * nc);
        const float nov  = fminf(fmaxf(1.f - cosv, 0.f), 2.f) * 0.5f;
        const float alpha = softplusf_(*p_la);
        const float sigma = softplusf_(*p_ls);
        s_gate = 1.f + alpha * tanhf(sigma * nov);
    }
    __syncthreads();
    const float g = s_gate;

    float4 o;
    o.x = gelu_tanh_(xv.x * g);
    o.y = gelu_tanh_(xv.y * g);
    o.z = gelu_tanh_(xv.z * g);
    o.w = gelu_tanh_(xv.w * g);
    *((float4*)out + (size_t)row * 256 + tid) = o;
}

// ---------------------------------------------------------------------------
extern "C" void kernel_launch(void* const* d_in, const int* in_sizes, int n_in,
                              void* d_out, int out_size) {
    const float* x  = (const float*)d_in[0];
    const float* la = (const float*)d_in[1];
    const float* ls = (const float*)d_in[2];
    float* out = (float*)d_out;

    const int qk_smem = NSTAGE * STAGE_BYTES;      // 73728
    const int av_smem = AV_NSTAGE * AV_STAGE;      // 196608
    cudaFuncSetAttribute(k_qk_mma, cudaFuncAttributeMaxDynamicSharedMemorySize, qk_smem);
    cudaFuncSetAttribute(k_av_mma, cudaFuncAttributeMaxDynamicSharedMemorySize, av_smem);

    dim3 gc(T_ / 32, D_ / 32, B_);
    k_cvt<<<gc, dim3(16, 16)>>>(x);

    dim3 g1(16, 32, B_);
    k_qk_mma<<<g1, 256, qk_smem>>>();

    k_denom<<<(B_ * T_) / 8, 256>>>();

    dim3 g3(4, 16, B_);
    k_av_mma<<<g3, 256, av_smem>>>();

    k_epi<<<B_ * T_, 256>>>(x, la, ls, out);
}

// round 8
// speedup vs baseline: 1.0912x; 1.0912x over previous
#include <cuda_runtime.h>
#include <cuda_bf16.h>
#include <cuda_fp16.h>
#include <stdint.h>

#define B_ 8
#define T_ 2048
#define D_ 1024
#define SCALE_ 0.03125f   // 1/sqrt(1024)

// k_qk config
#define NSTAGE 3
#define A_BYTES 8192        // 64 rows x 128B
#define B_BYTES 16384       // 128 rows x 128B
#define STAGE_BYTES (A_BYTES + B_BYTES)   // 24576

// k_av config (R4 structure)
#define AV_NSTAGE 3
#define AV_STAGE 32768      // 2 x (128 rows x 128B)

// ---------------------------------------------------------------------------
// Scratch
// ---------------------------------------------------------------------------
__device__ __nv_bfloat16 g_Xh [(size_t)B_ * T_ * D_];   // x bf16 (QK operands)
__device__ __half        g_XhT[(size_t)B_ * D_ * T_];   // x^T f16 (AV B operand)
__device__ __half        g_Sh [(size_t)B_ * T_ * T_];   // exp(masked logits), f16
__device__ float         g_C  [(size_t)B_ * T_ * D_];   // context fp32
__device__ float         g_den[B_ * T_];                // softmax denominators

// ---------------------------------------------------------------------------
// Helpers
// ---------------------------------------------------------------------------
__device__ __forceinline__ uint32_t smem_u32(const void* p) {
    uint32_t a;
    asm("{ .reg .u64 t; cvta.to.shared.u64 t, %1; cvt.u32.u64 %0, t; }"
        : "=r"(a) : "l"(p));
    return a;
}

__device__ __forceinline__ void cp16(uint32_t dst, const void* src) {
    asm volatile("cp.async.cg.shared.global [%0], [%1], 16;"
                 :: "r"(dst), "l"(src) : "memory");
}
#define CP_COMMIT() asm volatile("cp.async.commit_group;" ::: "memory")
#define CP_WAIT(N)  asm volatile("cp.async.wait_group %0;" :: "n"(N) : "memory")

__device__ __forceinline__ void ldmx4(uint32_t& r0, uint32_t& r1,
                                      uint32_t& r2, uint32_t& r3, uint32_t addr) {
    asm volatile("ldmatrix.sync.aligned.m8n8.x4.shared.b16 {%0,%1,%2,%3}, [%4];"
                 : "=r"(r0), "=r"(r1), "=r"(r2), "=r"(r3) : "r"(addr));
}

__device__ __forceinline__ void mma_bf16(float* c, const uint32_t* a,
                                         uint32_t b0, uint32_t b1) {
    asm volatile(
        "mma.sync.aligned.m16n8k16.row.col.f32.bf16.bf16.f32 "
        "{%0,%1,%2,%3}, {%4,%5,%6,%7}, {%8,%9}, {%0,%1,%2,%3};"
        : "+f"(c[0]), "+f"(c[1]), "+f"(c[2]), "+f"(c[3])
        : "r"(a[0]), "r"(a[1]), "r"(a[2]), "r"(a[3]), "r"(b0), "r"(b1));
}

__device__ __forceinline__ void mma_f16(float* c, const uint32_t* a,
                                        uint32_t b0, uint32_t b1) {
    asm volatile(
        "mma.sync.aligned.m16n8k16.row.col.f32.f16.f16.f32 "
        "{%0,%1,%2,%3}, {%4,%5,%6,%7}, {%8,%9}, {%0,%1,%2,%3};"
        : "+f"(c[0]), "+f"(c[1]), "+f"(c[2]), "+f"(c[3])
        : "r"(a[0]), "r"(a[1]), "r"(a[2]), "r"(a[3]), "r"(b0), "r"(b1));
}

__device__ __forceinline__ uint32_t sw128(uint32_t off) {
    return off ^ ((off >> 3) & 0x70);
}

__device__ __forceinline__ float softplusf_(float v) {
    return v > 20.f ? v : log1pf(__expf(v));
}
__device__ __forceinline__ float gelu_tanh_(float v) {
    float u = 0.7978845608028654f * (v + 0.044715f * v * v * v);
    return 0.5f * v * (1.f + tanhf(u));
}

// ---------------------------------------------------------------------------
// Kernel Z: zero denominators
// ---------------------------------------------------------------------------
__global__ void k_zero() {
    const int i = blockIdx.x * 1024 + threadIdx.x;
    if (i < B_ * T_) g_den[i] = 0.f;
}

// ---------------------------------------------------------------------------
// Kernel 0: convert x -> bf16 row-major + f16 transposed
// ---------------------------------------------------------------------------
__global__ __launch_bounds__(256) void k_cvt(const float* __restrict__ x) {
    __shared__ float tile[32][33];
    const int b  = blockIdx.z;
    const int t0 = blockIdx.x * 32;
    const int d0 = blockIdx.y * 32;
    const int lx = threadIdx.x;
    const int ly = threadIdx.y;
    const float* X = x + (size_t)b * T_ * D_;

#pragma unroll
    for (int r = 0; r < 2; r++) {
        const int t = t0 + ly + r * 16;
        const int d = d0 + lx * 2;
        float2 v = *(const float2*)(X + (size_t)t * D_ + d);
        __nv_bfloat162 h = __floats2bfloat162_rn(v.x, v.y);
        *(uint32_t*)(g_Xh + (size_t)(b * T_ + t) * D_ + d) = *(uint32_t*)&h;
        tile[ly + r * 16][lx * 2 + 0] = v.x;
        tile[ly + r * 16][lx * 2 + 1] = v.y;
    }
    __syncthreads();
#pragma unroll
    for (int r = 0; r < 2; r++) {
        const int d  = d0 + ly + r * 16;
        const int tp = lx * 2;
        __half2 h = __floats2half2_rn(tile[tp + 0][ly + r * 16],
                                      tile[tp + 1][ly + r * 16]);
        *(uint32_t*)(g_XhT + ((size_t)b * D_ + d) * T_ + t0 + tp) = *(uint32_t*)&h;
    }
}

// ---------------------------------------------------------------------------
// k_qk MMA core: CTA 64x128, 8 warps 2m x 4n of 32x32 (bf16 operands)
// ---------------------------------------------------------------------------
__device__ __forceinline__ void mma_chunk_qk(uint32_t sA, uint32_t sB,
                                             int warp_m, int warp_n, int lane,
                                             float c[2][4][4]) {
    const int rowsel = lane & 15;
    const int khalf  = (lane >> 4) * 16;
    const uint32_t a0 = sA + (warp_m * 32 + 0  + rowsel) * 128;
    const uint32_t a1 = sA + (warp_m * 32 + 16 + rowsel) * 128;
    const uint32_t b0a = sB + (warp_n * 32 + 0  + rowsel) * 128;
    const uint32_t b1a = sB + (warp_n * 32 + 16 + rowsel) * 128;
    const uint32_t xa0 = ((warp_m * 32 + 0  + rowsel) & 7) << 4;
    const uint32_t xa1 = ((warp_m * 32 + 16 + rowsel) & 7) << 4;
    const uint32_t xb0 = ((warp_n * 32 + 0  + rowsel) & 7) << 4;
    const uint32_t xb1 = ((warp_n * 32 + 16 + rowsel) & 7) << 4;
#pragma unroll
    for (int ks = 0; ks < 4; ks++) {
        const uint32_t kb = ks * 32 + khalf;
        uint32_t a[2][4];
        ldmx4(a[0][0], a[0][1], a[0][2], a[0][3], a0 + (kb ^ xa0));
        ldmx4(a[1][0], a[1][1], a[1][2], a[1][3], a1 + (kb ^ xa1));
        uint32_t b[4][2];
        {
            uint32_t r0, r1, r2, r3;
            ldmx4(r0, r1, r2, r3, b0a + (kb ^ xb0));
            b[0][0] = r0; b[1][0] = r1; b[0][1] = r2; b[1][1] = r3;
            ldmx4(r0, r1, r2, r3, b1a + (kb ^ xb1));
            b[2][0] = r0; b[3][0] = r1; b[2][1] = r2; b[3][1] = r3;
        }
#pragma unroll
        for (int mi = 0; mi < 2; mi++)
#pragma unroll
            for (int ni = 0; ni < 4; ni++)
                mma_bf16(c[mi][ni], a[mi], b[ni][0], b[ni][1]);
    }
}

__device__ __forceinline__ void load_tileA64(uint32_t sdst, const void* srcv,
                                             size_t row_stride_elts, int tid) {
    const __nv_bfloat16* src = (const __nv_bfloat16*)srcv;
    const int row = tid >> 2;
    const int cb  = (tid & 3) * 2;
    const __nv_bfloat16* g = src + (size_t)row * row_stride_elts + cb * 8;
#pragma unroll
    for (int c = 0; c < 2; c++)
        cp16(sdst + sw128(row * 128 + (cb + c) * 16), g + c * 8);
}
// 128 rows x 128B (any 2-byte type)
__device__ __forceinline__ void load_tileB128(uint32_t sdst, const void* srcv,
                                              size_t row_stride_elts, int tid) {
    const __half* src = (const __half*)srcv;
    const int row = tid >> 1;
    const int cb  = (tid & 1) * 4;
    const __half* g = src + (size_t)row * row_stride_elts + cb * 8;
#pragma unroll
    for (int c = 0; c < 4; c++)
        cp16(sdst + sw128(row * 128 + (cb + c) * 16), g + c * 8);
}

// ---------------------------------------------------------------------------
// Kernel 1: S = exp(SCALE * X X^T) f16, strict causal, fused row-sum -> g_den
// Mask applied to the exp ARGUMENT (z = -64 when masked): exp2(-64) == 0 in
// half, and the diagonal |x|^2 logit never reaches h2exp2 (avoids inf*0=NaN).
// ---------------------------------------------------------------------------
__global__ __launch_bounds__(256, 3) void k_qk_mma() {
    const int sb  = blockIdx.x;
    const int tb6 = blockIdx.y;
    const int b   = blockIdx.z;
    if (sb > (tb6 >> 1)) return;

    extern __shared__ __align__(1024) char smem[];
    __shared__ float rsum[64];
    const uint32_t sbase = smem_u32(smem);
    const int tid = threadIdx.x, lane = tid & 31, wid = tid >> 5;
    const int warp_m = wid & 1, warp_n = wid >> 1;

    if (tid < 64) rsum[tid] = 0.f;

    const __nv_bfloat16* A0 = g_Xh + (size_t)(b * T_ + tb6 * 64)  * D_;
    const __nv_bfloat16* B0 = g_Xh + (size_t)(b * T_ + sb * 128)  * D_;

    float c[2][4][4];
#pragma unroll
    for (int mi = 0; mi < 2; mi++)
#pragma unroll
        for (int ni = 0; ni < 4; ni++)
#pragma unroll
            for (int k = 0; k < 4; k++) c[mi][ni][k] = 0.f;

    const int nIter = D_ / 64;
#pragma unroll
    for (int s = 0; s < NSTAGE - 1; s++) {
        const uint32_t st = sbase + s * STAGE_BYTES;
        load_tileA64(st,            A0 + s * 64, D_, tid);
        load_tileB128(st + A_BYTES, B0 + s * 64, D_, tid);
        CP_COMMIT();
    }

    for (int it = 0; it < nIter; ++it) {
        if (it + NSTAGE - 1 < nIter) CP_WAIT(NSTAGE - 2); else CP_WAIT(0);
        __syncthreads();
        if (it + NSTAGE - 1 < nIter) {
            const int ld = it + NSTAGE - 1;
            const uint32_t stb = sbase + (ld % NSTAGE) * STAGE_BYTES;
            load_tileA64(stb,            A0 + ld * 64, D_, tid);
            load_tileB128(stb + A_BYTES, B0 + ld * 64, D_, tid);
            CP_COMMIT();
        }
        const uint32_t st = sbase + (it % NSTAGE) * STAGE_BYTES;
        mma_chunk_qk(st, st + A_BYTES, warp_m, warp_n, lane, c);
    }

    // epilogue: masked z -> packed f16 exp2 -> f16 store + fused row-sum
    const int quad = lane >> 2, qid = lane & 3;
    const float C2 = 0.045084219f;   // SCALE * log2(e)
#pragma unroll
    for (int mi = 0; mi < 2; mi++) {
        float rs[2] = {0.f, 0.f};
#pragma unroll
        for (int h = 0; h < 2; h++) {
            const int row = warp_m * 32 + mi * 16 + quad + h * 8;
            const int t   = tb6 * 64 + row;
#pragma unroll
            for (int ni = 0; ni < 4; ni++) {
                const int col = warp_n * 32 + ni * 8 + qid * 2;
                const int s0  = sb * 128 + col;
                const float z0 = (s0 + 0 < t) ? c[mi][ni][2 * h + 0] * C2 : -64.f;
                const float z1 = (s0 + 1 < t) ? c[mi][ni][2 * h + 1] * C2 : -64.f;
                __half2 e = h2exp2(__floats2half2_rn(z0, z1));
                *(uint32_t*)(g_Sh + ((size_t)(b * T_ + t)) * T_ + s0) = *(uint32_t*)&e;
                float2 ef = __half22float2(e);
                rs[h] += ef.x + ef.y;
            }
        }
#pragma unroll
        for (int h = 0; h < 2; h++) {
            float v = rs[h];
            v += __shfl_xor_sync(0xFFFFFFFFu, v, 1);
            v += __shfl_xor_sync(0xFFFFFFFFu, v, 2);
            if (qid == 0) {
                const int row = warp_m * 32 + mi * 16 + quad + h * 8;
                atomicAdd(&rsum[row], v);
            }
        }
    }
    __syncthreads();
    if (tid < 64)
        atomicAdd(&g_den[b * T_ + tb6 * 64 + tid], rsum[tid]);
}

// ---------------------------------------------------------------------------
// Kernel 3: context = (S @ X) / den. R4 config: CTA 128x128, 64x32 warps,
// 3-stage, 2 CTA/SM. f16 operands. Heavy tiles first.
// ---------------------------------------------------------------------------
__global__ __launch_bounds__(256) void k_av_mma() {
    const int nb = blockIdx.x;
    const int tb = (int)gridDim.y - 1 - (int)blockIdx.y;   // heavy-first
    const int b  = blockIdx.z;

    extern __shared__ __align__(1024) char smem[];
    const uint32_t sbase = smem_u32(smem);
    const int tid = threadIdx.x, lane = tid & 31, wid = tid >> 5;
    const int warp_m = wid & 1, warp_n = wid >> 1;

    const __half* A0 = g_Sh  + (size_t)(b * T_ + tb * 128) * T_;
    const __half* B0 = g_XhT + ((size_t)b * D_ + nb * 128) * T_;

    float c[4][4][4];
#pragma unroll
    for (int mi = 0; mi < 4; mi++)
#pragma unroll
        for (int ni = 0; ni < 4; ni++)
#pragma unroll
            for (int k = 0; k < 4; k++) c[mi][ni][k] = 0.f;

    const int nIter = (tb + 1) * 2;
#pragma unroll
    for (int s = 0; s < AV_NSTAGE - 1; s++) {
        if (s < nIter) {
            const uint32_t st = sbase + s * AV_STAGE;
            load_tileB128(st,         A0 + s * 64, T_, tid);
            load_tileB128(st + 16384, B0 + s * 64, T_, tid);
            CP_COMMIT();
        }
    }

    const int rowsel = lane & 15;
    const int khalf  = (lane >> 4) * 16;

    for (int it = 0; it < nIter; ++it) {
        if (it + AV_NSTAGE - 1 < nIter) CP_WAIT(AV_NSTAGE - 2); else CP_WAIT(0);
        __syncthreads();
        if (it + AV_NSTAGE - 1 < nIter) {
            const int ld = it + AV_NSTAGE - 1;
            const uint32_t stb = sbase + (ld % AV_NSTAGE) * AV_STAGE;
            load_tileB128(stb,         A0 + ld * 64, T_, tid);
            load_tileB128(stb + 16384, B0 + ld * 64, T_, tid);
            CP_COMMIT();
        }
        const uint32_t sA = sbase + (it % AV_NSTAGE) * AV_STAGE;
        const uint32_t sB = sA + 16384;
#pragma unroll
        for (int ks = 0; ks < 4; ks++) {
            const uint32_t kb = ks * 32 + khalf;
            uint32_t a[4][4];
#pragma unroll
            for (int mi = 0; mi < 4; mi++) {
                const uint32_t row = warp_m * 64 + mi * 16 + rowsel;
                ldmx4(a[mi][0], a[mi][1], a[mi][2], a[mi][3],
                      sA + row * 128 + (kb ^ ((row & 7) << 4)));
            }
            uint32_t bf[4][2];
#pragma unroll
            for (int nj = 0; nj < 2; nj++) {
                const uint32_t nrow = warp_n * 32 + nj * 16 + rowsel;
                uint32_t r0, r1, r2, r3;
                ldmx4(r0, r1, r2, r3, sB + nrow * 128 + (kb ^ ((nrow & 7) << 4)));
                bf[nj * 2 + 0][0] = r0; bf[nj * 2 + 1][0] = r1;
                bf[nj * 2 + 0][1] = r2; bf[nj * 2 + 1][1] = r3;
            }
#pragma unroll
            for (int mi = 0; mi < 4; mi++)
#pragma unroll
                for (int ni = 0; ni < 4; ni++)
                    mma_f16(c[mi][ni], a[mi], bf[ni][0], bf[ni][1]);
        }
    }

    // epilogue: divide by denom, fp32 store
    const int quad = lane >> 2, qid = lane & 3;
#pragma unroll
    for (int mi = 0; mi < 4; mi++) {
#pragma unroll
        for (int h = 0; h < 2; h++) {
            const int row = warp_m * 64 + mi * 16 + quad + h * 8;
            const int t   = tb * 128 + row;
            const float den = g_den[b * T_ + t];
            const float inv = den > 0.f ? 1.f / den : 0.f;
            float* crow = g_C + ((size_t)(b * T_ + t)) * D_ + nb * 128;
#pragma unroll
            for (int ni = 0; ni < 4; ni++) {
                const int col = warp_n * 32 + ni * 8 + qid * 2;
                float2 v;
                v.x = c[mi][ni][2 * h + 0] * inv;
                v.y = c[mi][ni][2 * h + 1] * inv;
                *(float2*)(crow + col) = v;
            }
        }
    }
}

// ---------------------------------------------------------------------------
// Kernel 4: cosine / novelty / gate / tanh-GELU
// ---------------------------------------------------------------------------
__global__ __launch_bounds__(256) void k_epi(const float* __restrict__ x,
                                             const float* __restrict__ p_la,
                                             const float* __restrict__ p_ls,
                                             float* __restrict__ out) {
    const int row = blockIdx.x;
    const int tid = threadIdx.x;
    const float4 xv = *((const float4*)x   + (size_t)row * 256 + tid);
    const float4 cv = *((const float4*)g_C + (size_t)row * 256 + tid);

    float xx = xv.x * xv.x + xv.y * xv.y + xv.z * xv.z + xv.w * xv.w;
    float cc = cv.x * cv.x + cv.y * cv.y + cv.z * cv.z + cv.w * cv.w;
    float xc = xv.x * cv.x + xv.y * cv.y + xv.z * cv.z + xv.w * cv.w;

#pragma unroll
    for (int o = 16; o; o >>= 1) {
        xx += __shfl_down_sync(0xFFFFFFFFu, xx, o);
        cc += __shfl_down_sync(0xFFFFFFFFu, cc, o);
        xc += __shfl_down_sync(0xFFFFFFFFu, xc, o);
    }

    __shared__ float s_xx[8], s_cc[8], s_xc[8];
    __shared__ float s_gate;
    const int lane = tid & 31, w = tid >> 5;
    if (lane == 0) { s_xx[w] = xx; s_cc[w] = cc; s_xc[w] = xc; }
    __syncthreads();
    if (tid == 0) {
        float fxx = 0.f, fcc = 0.f, fxc = 0.f;
#pragma unroll
        for (int k = 0; k < 8; k++) { fxx += s_xx[k]; fcc += s_cc[k]; fxc += s_xc[k]; }
        const float nx = fmaxf(sqrtf(fxx), 1e-12f);
        const float nc = fmaxf(sqrtf(fcc), 1e-12f);
        const float cosv = fxc / (nx * nc);
        const float nov  = fminf(fmaxf(1.f - cosv, 0.f), 2.f) * 0.5f;
        const float alpha = softplusf_(*p_la);
        const float sigma = softplusf_(*p_ls);
        s_gate = 1.f + alpha * tanhf(sigma * nov);
    }
    __syncthreads();
    const float g = s_gate;

    float4 o;
    o.x = gelu_tanh_(xv.x * g);
    o.y = gelu_tanh_(xv.y * g);
    o.z = gelu_tanh_(xv.z * g);
    o.w = gelu_tanh_(xv.w * g);
    *((float4*)out + (size_t)row * 256 + tid) = o;
}

// ---------------------------------------------------------------------------
extern "C" void kernel_launch(void* const* d_in, const int* in_sizes, int n_in,
                              void* d_out, int out_size) {
    const float* x  = (const float*)d_in[0];
    const float* la = (const float*)d_in[1];
    const float* ls = (const float*)d_in[2];
    float* out = (float*)d_out;

    const int qk_smem = NSTAGE * STAGE_BYTES;      // 73728
    const int av_smem = AV_NSTAGE * AV_STAGE;      // 98304
    cudaFuncSetAttribute(k_qk_mma, cudaFuncAttributeMaxDynamicSharedMemorySize, qk_smem);
    cudaFuncSetAttribute(k_av_mma, cudaFuncAttributeMaxDynamicSharedMemorySize, av_smem);

    k_zero<<<(B_ * T_ + 1023) / 1024, 1024>>>();

    dim3 gc(T_ / 32, D_ / 32, B_);
    k_cvt<<<gc, dim3(16, 16)>>>(x);

    dim3 g1(16, 32, B_);
    k_qk_mma<<<g1, 256, qk_smem>>>();

    dim3 g3(8, 16, B_);
    k_av_mma<<<g3, 256, av_smem>>>();

    k_epi<<<B_ * T_, 256>>>(x, la, ls, out);
}